// round 17
// baseline (speedup 1.0000x reference)
#include <cuda_runtime.h>
#include <cuda_fp16.h>

#define BATCH 4096
#define LSQ   64
#define HID   64
#define NFLD  11
#define LN    32
#define SROWS 32
#define SEQ_CTAS ((2 * BATCH) / SROWS)          // 256
#define NWF_CTAS (NFLD * (BATCH / 128))         // 352

// ---------------- scratch (no allocations allowed) ----------------
__device__ float g_m[2 * BATCH * HID];      // [from rows 0..4095 | to rows 4096..8191] x 64
__device__ float g_nwf[NFLD * BATCH * 8];   // [11][4096][8]

__constant__ int c_fm[11] = {0, 0, 1, 1, 2, 2, 3, 3, 4, 5, 5};

__device__ __forceinline__ float tanh_hw(float x) {
    float y; asm("tanh.approx.f32 %0, %1;" : "=f"(y) : "f"(x)); return y;
}
__device__ __forceinline__ float sig_hw(float x) {
    return fmaf(tanh_hw(0.5f * x), 0.5f, 0.5f);
}

// smem overlay: seq role ~20.5KB, nwf role ~40KB -> union sized by nwf
struct SeqS {
    __half  hbuf[2][SROWS][88];
    int     tok[SROWS][LSQ];
    __half2 ebase[85][3];
};
struct NwfS {
    int    ns[LN][132];
    int    fs[LN][132];
    __half At[8][16][24];
};
union MainS { SeqS s; NwfS n; };

// ================= fused kernel: seq CTAs (bid<256) + nwf CTAs =================
__global__ void __launch_bounds__(256, 2) k_main(
    const int* __restrict__ from_seq, const int* __restrict__ to_seq,
    const float* __restrict__ Wh, const float* __restrict__ Wx,
    const float* __restrict__ bias, const float* __restrict__ base_emb,
    const int* __restrict__ nums_g, const int* __restrict__ frs_g,
    const float* __restrict__ ne_g, const float* __restrict__ fe_g,
    const float* __restrict__ nWx_g, const float* __restrict__ nWh_g,
    const float* __restrict__ nb_g)
{
    __shared__ alignas(16) MainS sm;
    const int tid  = threadIdx.x;
    const int lane = tid & 31;
    const int w    = tid >> 5;
    const int gid  = lane >> 2;
    const int tig  = lane & 3;

    if (blockIdx.x < SEQ_CTAS) {
        // ---------------- seq role: proven 83us tensor-core LSTM ----------------
        SeqS* ss = &sm.s;
        const int row0 = blockIdx.x * SROWS;

        const int* seq = (row0 < BATCH) ? (from_seq + row0 * LSQ)
                                        : (to_seq + (row0 - BATCH) * LSQ);
        for (int i = tid; i < SROWS * LSQ; i += 256) ss->tok[i >> 6][i & 63] = seq[i];
        for (int i = tid; i < 2 * SROWS * 88; i += 256)
            (&ss->hbuf[0][0][0])[i] = __float2half(0.0f);
        for (int i = tid; i < 85 * 3; i += 256) {
            int v = i / 3, p = i % 3;
            ss->ebase[v][p] = __floats2half2_rn(base_emb[v * 6 + 2 * p], base_emb[v * 6 + 2 * p + 1]);
        }
        __syncthreads();
        if (tid < 64) ss->hbuf[tid >> 5][tid & 31][70] = __float2half(1.0f);
        if (tid < 96) {
            int r = tid / 3, p = tid % 3;
            *reinterpret_cast<__half2*>(&ss->hbuf[0][r][64 + 2 * p]) = ss->ebase[ss->tok[r][0]][p];
        }

        unsigned bfr[4][5][2];
#pragma unroll
        for (int g = 0; g < 4; g++) {
            const int col = 64 * g + 8 * w + gid;
#pragma unroll
            for (int kt = 0; kt < 4; kt++) {
                int k0 = 16 * kt + 2 * tig;
                __half2 b0 = __floats2half2_rn(Wh[k0 * 256 + col], Wh[(k0 + 1) * 256 + col]);
                __half2 b1 = __floats2half2_rn(Wh[(k0 + 8) * 256 + col], Wh[(k0 + 9) * 256 + col]);
                bfr[g][kt][0] = *reinterpret_cast<unsigned*>(&b0);
                bfr[g][kt][1] = *reinterpret_cast<unsigned*>(&b1);
            }
            {
                int r0 = 64 + 2 * tig;
                float v0 = (r0 < 70) ? Wx[(r0 - 64) * 256 + col] : ((r0 == 70) ? bias[col] : 0.0f);
                float v1 = (r0 + 1 < 70) ? Wx[(r0 - 63) * 256 + col] : ((r0 + 1 == 70) ? bias[col] : 0.0f);
                __half2 b0 = __floats2half2_rn(v0, v1);
                bfr[g][4][0] = *reinterpret_cast<unsigned*>(&b0);
                bfr[g][4][1] = 0u;
            }
        }

        const int hc0 = 8 * w + 2 * tig;
        const int arow = (lane < 16) ? lane : (lane - 16);
        const int acol = (lane < 16) ? 0 : 8;
        const unsigned a00 = (unsigned)__cvta_generic_to_shared(&ss->hbuf[0][arow][acol]);
        const unsigned a01 = (unsigned)__cvta_generic_to_shared(&ss->hbuf[0][16 + arow][acol]);
        const unsigned a10 = (unsigned)__cvta_generic_to_shared(&ss->hbuf[1][arow][acol]);
        const unsigned a11 = (unsigned)__cvta_generic_to_shared(&ss->hbuf[1][16 + arow][acol]);

        float cst[8] = {0.0f, 0.0f, 0.0f, 0.0f, 0.0f, 0.0f, 0.0f, 0.0f};

        __syncthreads();

        for (int t = 0; t < LSQ; t++) {
            const unsigned r0a = (t & 1) ? a10 : a00;
            const unsigned r1a = (t & 1) ? a11 : a01;

            float d0[4][4], d1[4][4];
#pragma unroll
            for (int g = 0; g < 4; g++)
#pragma unroll
                for (int q = 0; q < 4; q++) { d0[g][q] = 0.0f; d1[g][q] = 0.0f; }

#pragma unroll
            for (int kt = 0; kt < 5; kt++) {
                unsigned ah0[4], ah1[4];
                asm volatile("ldmatrix.sync.aligned.m8n8.x4.shared.b16 {%0,%1,%2,%3}, [%4];\n"
                             : "=r"(ah0[0]), "=r"(ah0[1]), "=r"(ah0[2]), "=r"(ah0[3])
                             : "r"(r0a + kt * 32));
                asm volatile("ldmatrix.sync.aligned.m8n8.x4.shared.b16 {%0,%1,%2,%3}, [%4];\n"
                             : "=r"(ah1[0]), "=r"(ah1[1]), "=r"(ah1[2]), "=r"(ah1[3])
                             : "r"(r1a + kt * 32));
#pragma unroll
                for (int g = 0; g < 4; g++) {
                    asm("mma.sync.aligned.m16n8k16.row.col.f32.f16.f16.f32 "
                        "{%0,%1,%2,%3},{%4,%5,%6,%7},{%8,%9},{%0,%1,%2,%3};\n"
                        : "+f"(d0[g][0]), "+f"(d0[g][1]), "+f"(d0[g][2]), "+f"(d0[g][3])
                        : "r"(ah0[0]), "r"(ah0[1]), "r"(ah0[2]), "r"(ah0[3]),
                          "r"(bfr[g][kt][0]), "r"(bfr[g][kt][1]));
                    asm("mma.sync.aligned.m16n8k16.row.col.f32.f16.f16.f32 "
                        "{%0,%1,%2,%3},{%4,%5,%6,%7},{%8,%9},{%0,%1,%2,%3};\n"
                        : "+f"(d1[g][0]), "+f"(d1[g][1]), "+f"(d1[g][2]), "+f"(d1[g][3])
                        : "r"(ah1[0]), "r"(ah1[1]), "r"(ah1[2]), "r"(ah1[3]),
                          "r"(bfr[g][kt][0]), "r"(bfr[g][kt][1]));
                }
            }

            float hv[8];
#pragma unroll
            for (int q = 0; q < 4; q++) {
                cst[q] = sig_hw(d0[1][q]) * cst[q] + sig_hw(d0[0][q]) * tanh_hw(d0[2][q]);
                hv[q]  = sig_hw(d0[3][q]) * tanh_hw(cst[q]);
            }
#pragma unroll
            for (int q = 0; q < 4; q++) {
                cst[4 + q] = sig_hw(d1[1][q]) * cst[4 + q] + sig_hw(d1[0][q]) * tanh_hw(d1[2][q]);
                hv[4 + q]  = sig_hw(d1[3][q]) * tanh_hw(cst[4 + q]);
            }

            const int wb = (t & 1) ^ 1;
            *reinterpret_cast<__half2*>(&ss->hbuf[wb][gid][hc0])      = __floats2half2_rn(hv[0], hv[1]);
            *reinterpret_cast<__half2*>(&ss->hbuf[wb][gid + 8][hc0])  = __floats2half2_rn(hv[2], hv[3]);
            *reinterpret_cast<__half2*>(&ss->hbuf[wb][gid + 16][hc0]) = __floats2half2_rn(hv[4], hv[5]);
            *reinterpret_cast<__half2*>(&ss->hbuf[wb][gid + 24][hc0]) = __floats2half2_rn(hv[6], hv[7]);
            if (t < LSQ - 1 && tid < 96) {
                int r = tid / 3, p = tid % 3;
                *reinterpret_cast<__half2*>(&ss->hbuf[wb][r][64 + 2 * p]) = ss->ebase[ss->tok[r][t + 1]][p];
            }

            if (t == LSQ - 1) {
                *reinterpret_cast<float2*>(&g_m[(row0 + gid) * 64 + hc0])      = make_float2(hv[0], hv[1]);
                *reinterpret_cast<float2*>(&g_m[(row0 + gid + 8) * 64 + hc0])  = make_float2(hv[2], hv[3]);
                *reinterpret_cast<float2*>(&g_m[(row0 + gid + 16) * 64 + hc0]) = make_float2(hv[4], hv[5]);
                *reinterpret_cast<float2*>(&g_m[(row0 + gid + 24) * 64 + hc0]) = make_float2(hv[6], hv[7]);
            }
            __syncthreads();
        }
    } else {
        // ---------------- nwf role: proven tensor-core NWF LSTMs ----------------
        NwfS* ns = &sm.n;
        const int bi = blockIdx.x - SEQ_CTAS;   // 0..351
        const int field = bi >> 5;              // 11 fields x 32 tiles
        const int tile  = bi & 31;
        const int m = c_fm[field];
        const int row0 = tile * 128;

        const int base = (field * BATCH + row0) * LN;
        for (int i = tid; i < 128 * LN; i += 256) {
            int r = i >> 5, t = i & 31;
            ns->ns[t][r] = nums_g[base + i];
            ns->fs[t][r] = frs_g[base + i];
        }
        for (int i = tid; i < 8 * 16 * 24 / 2; i += 256)
            reinterpret_cast<__half2*>(&ns->At[0][0][0])[i] = __floats2half2_rn(0.0f, 0.0f);
        __syncthreads();

        unsigned bf[4][2];
        float2 b2[4];
#pragma unroll
        for (int g = 0; g < 4; g++) {
            const int col = 8 * g + gid;
            __half2 x0 = __floats2half2_rn(nWx_g[m * 256 + (2 * tig) * 32 + col],
                                           nWx_g[m * 256 + (2 * tig + 1) * 32 + col]);
            __half2 h0 = __floats2half2_rn(nWh_g[m * 256 + (2 * tig) * 32 + col],
                                           nWh_g[m * 256 + (2 * tig + 1) * 32 + col]);
            bf[g][0] = *reinterpret_cast<unsigned*>(&x0);
            bf[g][1] = *reinterpret_cast<unsigned*>(&h0);
            b2[g] = make_float2(nb_g[m * 32 + 8 * g + 2 * tig], nb_g[m * 32 + 8 * g + 2 * tig + 1]);
        }

        const float4* neg = reinterpret_cast<const float4*>(ne_g) + m * 1000;
        const float4* feg = reinterpret_cast<const float4*>(fe_g) + m * 1000;

        const int lrow = lane & 15;
        const bool isNe = (lane < 16);
        const int myrow = w * 16 + lrow;
        const int xcol = isNe ? 0 : 4;
        const unsigned aaddr = (unsigned)__cvta_generic_to_shared(&ns->At[w][lrow][isNe ? 0 : 8]);

        float cst[4] = {0.0f, 0.0f, 0.0f, 0.0f};
        float hv[4] = {0.0f, 0.0f, 0.0f, 0.0f};

        for (int t = 0; t < LN; t++) {
            int idx = isNe ? ns->ns[t][myrow] : ns->fs[t][myrow];
            float4 v = __ldg(isNe ? &neg[idx] : &feg[idx]);
            *reinterpret_cast<__half2*>(&ns->At[w][lrow][xcol])     = __floats2half2_rn(v.x, v.y);
            *reinterpret_cast<__half2*>(&ns->At[w][lrow][xcol + 2]) = __floats2half2_rn(v.z, v.w);
            __syncwarp();

            unsigned a[4];
            asm volatile("ldmatrix.sync.aligned.m8n8.x4.shared.b16 {%0,%1,%2,%3}, [%4];\n"
                         : "=r"(a[0]), "=r"(a[1]), "=r"(a[2]), "=r"(a[3]) : "r"(aaddr));

            float d[4][4];
#pragma unroll
            for (int g = 0; g < 4; g++) {
                d[g][0] = 0.0f; d[g][1] = 0.0f; d[g][2] = 0.0f; d[g][3] = 0.0f;
                asm("mma.sync.aligned.m16n8k16.row.col.f32.f16.f16.f32 "
                    "{%0,%1,%2,%3},{%4,%5,%6,%7},{%8,%9},{%0,%1,%2,%3};\n"
                    : "+f"(d[g][0]), "+f"(d[g][1]), "+f"(d[g][2]), "+f"(d[g][3])
                    : "r"(a[0]), "r"(a[1]), "r"(a[2]), "r"(a[3]),
                      "r"(bf[g][0]), "r"(bf[g][1]));
            }

#pragma unroll
            for (int q = 0; q < 4; q++) {
                float bi2 = (q & 1) ? b2[0].y : b2[0].x;
                float bff = (q & 1) ? b2[1].y : b2[1].x;
                float bgg = (q & 1) ? b2[2].y : b2[2].x;
                float bo = (q & 1) ? b2[3].y : b2[3].x;
                float gi = d[0][q] + bi2, gf = d[1][q] + bff, gg = d[2][q] + bgg, go = d[3][q] + bo;
                cst[q] = sig_hw(gf) * cst[q] + sig_hw(gi) * tanh_hw(gg);
                hv[q]  = sig_hw(go) * tanh_hw(cst[q]);
            }

            *reinterpret_cast<__half2*>(&ns->At[w][gid][8 + 2 * tig])     = __floats2half2_rn(hv[0], hv[1]);
            *reinterpret_cast<__half2*>(&ns->At[w][gid + 8][8 + 2 * tig]) = __floats2half2_rn(hv[2], hv[3]);
        }

        float* o = &g_nwf[(field * BATCH + row0 + w * 16) * 8];
        *reinterpret_cast<float2*>(&o[gid * 8 + 2 * tig])       = make_float2(hv[0], hv[1]);
        *reinterpret_cast<float2*>(&o[(gid + 8) * 8 + 2 * tig]) = make_float2(hv[2], hv[3]);
    }
}

// ---------------- kernel 2: slot-staged concat + split-K dense 234->64 + ReLU ----------------
// 1024 threads, 16 rows/CTA, grid 256. GEMM phase: thread = (row, colpair, khalf),
// each sums 117 features -> half the latency chain, ~2x occupancy. Partials
// combined via smem by the first 512 threads.
__global__ void __launch_bounds__(1024) k_final(const float* __restrict__ goby_emb,
                                                const float* __restrict__ bool_emb,
                                                const float* __restrict__ count_emb,
                                                const float* __restrict__ W,
                                                const float* __restrict__ bias,
                                                const int* __restrict__ goby_idx,
                                                const int* __restrict__ is_indel,
                                                const int* __restrict__ matches_ref,
                                                const int* __restrict__ count_fwd,
                                                const int* __restrict__ count_rev,
                                                float* __restrict__ out) {
    const int tid = threadIdx.x;
    const int row0 = blockIdx.x * 16;
    __shared__ float  fsh[16][240];
    __shared__ float2 psum[16][64];

    {   // staging: one pass, 1024 slots = 16 rows x 64 slots (R15 slot map)
        const int rr = tid >> 6;
        const int row = row0 + rr;
        const int slot = tid & 63;
        if (slot >= 4 && slot < 36) {
            int q = slot - 4;
            const float* src = (q < 16) ? &g_m[row * 64 + 4 * q]
                                        : &g_m[(BATCH + row) * 64 + 4 * (q - 16)];
            float4 v = *reinterpret_cast<const float4*>(src);
            int o = (q < 16) ? (8 + 4 * q) : (72 + 4 * (q - 16));
            *reinterpret_cast<float4*>(&fsh[rr][o]) = v;
        } else if (slot >= 36 && slot < 58) {
            int q = slot - 36;
            int field = q >> 1;
            float4 v = *reinterpret_cast<const float4*>(
                &g_nwf[((field * BATCH) + row) * 8 + 4 * (q & 1)]);
            int o = 146 + 4 * q;
            *reinterpret_cast<float2*>(&fsh[rr][o])     = make_float2(v.x, v.y);
            *reinterpret_cast<float2*>(&fsh[rr][o + 2]) = make_float2(v.z, v.w);
        } else if (slot == 0) {
            float4 v = *reinterpret_cast<const float4*>(&goby_emb[goby_idx[row] * 4]);
            *reinterpret_cast<float4*>(&fsh[rr][0]) = v;
        } else if (slot == 1) {
            float2 bi = *reinterpret_cast<const float2*>(&bool_emb[is_indel[row] * 2]);
            float2 bm = *reinterpret_cast<const float2*>(&bool_emb[matches_ref[row] * 2]);
            *reinterpret_cast<float2*>(&fsh[rr][4]) = bi;
            *reinterpret_cast<float2*>(&fsh[rr][6]) = bm;
        } else if (slot == 2) {
            const float* s = &count_emb[count_fwd[row] * 5];
#pragma unroll
            for (int j = 0; j < 5; j++) fsh[rr][136 + j] = s[j];
        } else if (slot == 3) {
            const float* s = &count_emb[count_rev[row] * 5];
#pragma unroll
            for (int j = 0; j < 5; j++) fsh[rr][141 + j] = s[j];
        }
    }
    __syncthreads();

    {   // split-K GEMM: rr 0..15, cp 0..31, kh 0..1; f in [117*kh, 117*kh+117)
        const int rr = tid >> 6;
        const int t6 = tid & 63;
        const int cp = t6 >> 1;
        const int kh = t6 & 1;
        const float2* W2 = reinterpret_cast<const float2*>(W);
        float2 acc = make_float2(0.0f, 0.0f);
        const int f0 = 117 * kh;
#pragma unroll 9
        for (int f = f0; f < f0 + 117; f++) {
            float v = fsh[rr][f];
            float2 wv = __ldg(&W2[f * 32 + cp]);
            acc.x = fmaf(v, wv.x, acc.x);
            acc.y = fmaf(v, wv.y, acc.y);
        }
        psum[rr][t6] = acc;
    }
    __syncthreads();

    if (tid < 512) {   // combine halves + bias + relu + store
        const int rr = tid >> 5;
        const int cp = tid & 31;
        float2 a = psum[rr][2 * cp];
        float2 b = psum[rr][2 * cp + 1];
        float2 bs = *reinterpret_cast<const float2*>(&bias[2 * cp]);
        float ox = fmaxf(a.x + b.x + bs.x, 0.0f);
        float oy = fmaxf(a.y + b.y + bs.y, 0.0f);
        *reinterpret_cast<float2*>(&out[(row0 + rr) * 64 + 2 * cp]) = make_float2(ox, oy);
    }
}

// ---------------- launch ----------------
extern "C" void kernel_launch(void* const* d_in, const int* in_sizes, int n_in,
                              void* d_out, int out_size) {
    static const int dictmap[23]  = {0,1,2,3,4,5,6,7,8,9,10,11,12,13,14,15,16,17,18,19,20,21,22};
    static const int parammap[23] = {14,15,16,17,18,19,20,21,22,0,1,2,3,4,5,6,7,8,9,10,11,12,13};
    const int* mp = (in_sizes[0] == BATCH) ? dictmap : parammap;

    const int*   goby_idx     = (const int*)  d_in[mp[0]];
    const int*   is_indel     = (const int*)  d_in[mp[1]];
    const int*   matches_ref  = (const int*)  d_in[mp[2]];
    const int*   from_seq     = (const int*)  d_in[mp[3]];
    const int*   to_seq       = (const int*)  d_in[mp[4]];
    const int*   count_fwd    = (const int*)  d_in[mp[5]];
    const int*   count_rev    = (const int*)  d_in[mp[6]];
    const int*   nwf_numbers  = (const int*)  d_in[mp[7]];
    const int*   nwf_freqs    = (const int*)  d_in[mp[8]];
    const float* goby_emb     = (const float*)d_in[mp[9]];
    const float* bool_emb     = (const float*)d_in[mp[10]];
    const float* count_emb    = (const float*)d_in[mp[11]];
    const float* base_emb     = (const float*)d_in[mp[12]];
    const float* seq_Wx       = (const float*)d_in[mp[13]];
    const float* seq_Wh       = (const float*)d_in[mp[14]];
    const float* seq_b        = (const float*)d_in[mp[15]];
    const float* nwf_num_emb  = (const float*)d_in[mp[16]];
    const float* nwf_freq_emb = (const float*)d_in[mp[17]];
    const float* nwf_Wx       = (const float*)d_in[mp[18]];
    const float* nwf_Wh       = (const float*)d_in[mp[19]];
    const float* nwf_b        = (const float*)d_in[mp[20]];
    const float* reduce_W     = (const float*)d_in[mp[21]];
    const float* reduce_b     = (const float*)d_in[mp[22]];

    k_main<<<SEQ_CTAS + NWF_CTAS, 256>>>(from_seq, to_seq, seq_Wh, seq_Wx, seq_b, base_emb,
                                         nwf_numbers, nwf_freqs, nwf_num_emb, nwf_freq_emb,
                                         nwf_Wx, nwf_Wh, nwf_b);
    k_final<<<BATCH / 16, 1024>>>(goby_emb, bool_emb, count_emb, reduce_W, reduce_b,
                                  goby_idx, is_indel, matches_ref, count_fwd, count_rev,
                                  (float*)d_out);
}